// round 1
// baseline (speedup 1.0000x reference)
#include <cuda_runtime.h>
#include <math.h>

// Problem constants (fixed shapes per reference)
#define M_TOT   8192
#define NREL    64
#define D       128
#define TM      32          // m-rows per tile
#define MAXT    320         // sum ceil(cnt/TM) <= 8192/32 + 64 = 320
#define THREADS 256
#define REG_LAMBDA 1e-5

// ---------------- device scratch (no allocations allowed) ----------------
__device__ int   g_cnt[NREL];
__device__ int   g_off[NREL];
__device__ int   g_cur[NREL];
__device__ int   g_sorted[M_TOT];
__device__ int   g_tile_rel[MAXT];
__device__ int   g_tile_start[MAXT];
__device__ int   g_tile_cnt[MAXT];
__device__ float g_loss[M_TOT];
__device__ float g_reg[M_TOT];

// ---------------- tiny setup kernels ----------------
__global__ void k_init() {
    int t = threadIdx.x;
    if (t < NREL) { g_cnt[t] = 0; g_cur[t] = 0; }
}

__global__ void k_hist(const int* __restrict__ r) {
    int m = blockIdx.x * blockDim.x + threadIdx.x;
    if (m < M_TOT) atomicAdd(&g_cnt[r[m]], 1);
}

__global__ void k_plan() {
    if (threadIdx.x != 0 || blockIdx.x != 0) return;
    int off = 0, nt = 0;
    for (int rel = 0; rel < NREL; rel++) {
        g_off[rel] = off;
        int c = g_cnt[rel];
        int t = 0;
        while (t < c) {
            g_tile_rel[nt]   = rel;
            g_tile_start[nt] = off + t;
            g_tile_cnt[nt]   = min(TM, c - t);
            nt++;
            t += TM;
        }
        off += c;
    }
    for (; nt < MAXT; nt++) g_tile_cnt[nt] = 0;
}

__global__ void k_scatter(const int* __restrict__ r) {
    int m = blockIdx.x * blockDim.x + threadIdx.x;
    if (m < M_TOT) {
        int rel = r[m];
        int p = atomicAdd(&g_cur[rel], 1);
        g_sorted[g_off[rel] + p] = m;
    }
}

// ---------------- main fused kernel ----------------
struct SmemLayout {
    float W[D * D];       // 64 KB, layout [e][j]
    float u[TM * D];      // (h - pos_t) rows
    float v[TM * D];      // (h - neg_t) rows
    float rsh[D];         // relation embedding
    int   msh[TM];        // original m index per slot
    int   hidx[TM];
    int   pidx[TM];
    int   nidx[TM];
    float regsh[TM];      // sum of squares of h,p,n embeds per m
    float rsq;            // sum of squares of r embed
};

__global__ void __launch_bounds__(THREADS, 2) k_main(
    const int*   __restrict__ h,
    const int*   __restrict__ pos_t,
    const int*   __restrict__ neg_t,
    const float* __restrict__ ent,
    const float* __restrict__ rel_emb,
    const float* __restrict__ rel_w)
{
    extern __shared__ char smem_raw[];
    SmemLayout& S = *reinterpret_cast<SmemLayout*>(smem_raw);

    int tile = blockIdx.x;
    int cnt  = g_tile_cnt[tile];
    if (cnt == 0) return;
    int rel   = g_tile_rel[tile];
    int start = g_tile_start[tile];
    int tid   = threadIdx.x;

    // Stage indices + relation embedding + W (W is L2-hot: only 64 relations)
    if (tid < TM) {
        S.regsh[tid] = 0.f;
        if (tid < cnt) {
            int mo = g_sorted[start + tid];
            S.msh[tid]  = mo;
            S.hidx[tid] = h[mo];
            S.pidx[tid] = pos_t[mo];
            S.nidx[tid] = neg_t[mo];
        }
    }
    if (tid < D) S.rsh[tid] = rel_emb[rel * D + tid];

    const float4* Wg  = reinterpret_cast<const float4*>(rel_w + (size_t)rel * D * D);
    float4*       Ws4 = reinterpret_cast<float4*>(S.W);
    #pragma unroll
    for (int t = tid; t < (D * D) / 4; t += THREADS) Ws4[t] = Wg[t];
    __syncthreads();

    // rsq: warp 0 computes sum(r^2)
    if (tid < 32) {
        float s = 0.f;
        #pragma unroll
        for (int j = tid; j < D; j += 32) { float rv = S.rsh[j]; s += rv * rv; }
        #pragma unroll
        for (int o = 16; o; o >>= 1) s += __shfl_xor_sync(0xffffffffu, s, o);
        if (tid == 0) S.rsq = s;
    }

    // Gather embeddings, form u = h - p, v = h - n, accumulate reg squares.
    // idx maps so each warp iteration covers one (i, 32-consecutive-e) block.
    for (int idx = tid; idx < TM * D; idx += THREADS) {
        int i = idx >> 7;
        int e = idx & (D - 1);
        float uo = 0.f, vo = 0.f, sq = 0.f;
        if (i < cnt) {
            float he = ent[(size_t)S.hidx[i] * D + e];
            float pe = ent[(size_t)S.pidx[i] * D + e];
            float ne = ent[(size_t)S.nidx[i] * D + e];
            uo = he - pe;
            vo = he - ne;
            sq = he * he + pe * pe + ne * ne;
        }
        S.u[idx] = uo;
        S.v[idx] = vo;
        #pragma unroll
        for (int o = 16; o; o >>= 1) sq += __shfl_xor_sync(0xffffffffu, sq, o);
        if ((tid & 31) == 0 && i < cnt) atomicAdd(&S.regsh[i], sq);
    }
    __syncthreads();

    // Compute phase: warp mt handles m = mt + 8k (k<4); lane jt handles j = 4*jt..4*jt+3.
    int jt = tid & 31;
    int mt = tid >> 5;
    float rj[4];
    #pragma unroll
    for (int jj = 0; jj < 4; jj++) rj[jj] = S.rsh[jt * 4 + jj];

    float a[4][4];   // a[jj][k] = (u_m W)_j
    float b[4][4];
    #pragma unroll
    for (int jj = 0; jj < 4; jj++)
        #pragma unroll
        for (int k = 0; k < 4; k++) { a[jj][k] = 0.f; b[jj][k] = 0.f; }

    const float4* Wv = reinterpret_cast<const float4*>(S.W);
    #pragma unroll 4
    for (int e = 0; e < D; e++) {
        float4 w = Wv[e * 32 + jt];            // coalesced float4 LDS
        #pragma unroll
        for (int k = 0; k < 4; k++) {
            float uk = S.u[(mt + 8 * k) * D + e];  // warp-broadcast LDS
            float vk = S.v[(mt + 8 * k) * D + e];
            a[0][k] += uk * w.x; a[1][k] += uk * w.y;
            a[2][k] += uk * w.z; a[3][k] += uk * w.w;
            b[0][k] += vk * w.x; b[1][k] += vk * w.y;
            b[2][k] += vk * w.z; b[3][k] += vk * w.w;
        }
    }

    #pragma unroll
    for (int k = 0; k < 4; k++) {
        int i = mt + 8 * k;
        float pos = 0.f, neg = 0.f;
        #pragma unroll
        for (int jj = 0; jj < 4; jj++) {
            float da = a[jj][k] + rj[jj];
            float db = b[jj][k] + rj[jj];
            pos += da * da;
            neg += db * db;
        }
        #pragma unroll
        for (int o = 16; o; o >>= 1) {
            pos += __shfl_xor_sync(0xffffffffu, pos, o);
            neg += __shfl_xor_sync(0xffffffffu, neg, o);
        }
        if (jt == 0 && i < cnt) {
            int mo = S.msh[i];
            float x = 0.5f * (pos - neg);                 // pos_score - neg_score
            float loss = fmaxf(-x, 0.f) + log1pf(expf(-fabsf(x)));  // softplus(-x)
            g_loss[mo] = loss;
            g_reg[mo]  = 0.5f * (S.regsh[i] + S.rsq);
        }
    }
}

// ---------------- final reduction ----------------
__global__ void k_reduce(float* __restrict__ out) {
    __shared__ double sl[256];
    __shared__ double sr[256];
    int tid = threadIdx.x;
    double l = 0.0, rg = 0.0;
    for (int i = tid; i < M_TOT; i += 256) {
        l  += (double)g_loss[i];
        rg += (double)g_reg[i];
    }
    sl[tid] = l; sr[tid] = rg;
    __syncthreads();
    for (int s = 128; s; s >>= 1) {
        if (tid < s) { sl[tid] += sl[tid + s]; sr[tid] += sr[tid + s]; }
        __syncthreads();
    }
    if (tid == 0) {
        double kg_loss = sl[0] / (double)M_TOT;
        double reg     = sr[0] / (double)M_TOT;
        out[0] = (float)(kg_loss + REG_LAMBDA * reg);
    }
}

// ---------------- launch ----------------
extern "C" void kernel_launch(void* const* d_in, const int* in_sizes, int n_in,
                              void* d_out, int out_size) {
    const int*   h       = (const int*)d_in[0];
    const int*   r       = (const int*)d_in[1];
    const int*   pos_t   = (const int*)d_in[2];
    const int*   neg_t   = (const int*)d_in[3];
    const float* ent     = (const float*)d_in[4];
    const float* rel_emb = (const float*)d_in[5];
    const float* rel_w   = (const float*)d_in[6];
    float* out = (float*)d_out;

    const int smem_bytes = (int)sizeof(SmemLayout);
    cudaFuncSetAttribute(k_main, cudaFuncAttributeMaxDynamicSharedMemorySize, smem_bytes);

    k_init<<<1, 64>>>();
    k_hist<<<M_TOT / 256, 256>>>(r);
    k_plan<<<1, 32>>>();
    k_scatter<<<M_TOT / 256, 256>>>(r);
    k_main<<<MAXT, THREADS, smem_bytes>>>(h, pos_t, neg_t, ent, rel_emb, rel_w);
    k_reduce<<<1, 256>>>(out);
}

// round 2
// speedup vs baseline: 1.0500x; 1.0500x over previous
#include <cuda_runtime.h>
#include <math.h>

// Fixed problem shapes
#define M_TOT   8192
#define NREL    64
#define D       128
#define TM      32          // m-rows per tile
#define MAXT    320         // sum ceil(cnt/TM) <= 8192/32 + 64 = 320 (exact bound)
#define THREADS 256
#define REG_LAMBDA 1e-5

// ---------------- device scratch (no allocations allowed) ----------------
__device__ int   g_sorted[M_TOT];
__device__ int   g_tile_rel[MAXT];
__device__ int   g_tile_start[MAXT];
__device__ int   g_tile_cnt[MAXT];
__device__ float g_loss[M_TOT];
__device__ float g_reg[M_TOT];
__device__ unsigned int g_done;

// ---------------- packed f32x2 helpers (FFMA2 path, sm_10x) ----------------
__device__ __forceinline__ unsigned long long pack2(float x, float y) {
    unsigned long long r;
    asm("mov.b64 %0, {%1, %2};" : "=l"(r) : "f"(x), "f"(y));
    return r;
}
__device__ __forceinline__ unsigned long long fma2(unsigned long long a,
                                                   unsigned long long b,
                                                   unsigned long long c) {
    unsigned long long d;
    asm("fma.rn.f32x2 %0, %1, %2, %3;" : "=l"(d) : "l"(a), "l"(b), "l"(c));
    return d;
}
__device__ __forceinline__ void unpack2(unsigned long long v, float& lo, float& hi) {
    asm("mov.b64 {%0, %1}, %2;" : "=f"(lo), "=f"(hi) : "l"(v));
}

// ---------------- fused setup: hist + scan + tile plan + counting-sort ----------------
__global__ void k_setup(const int* __restrict__ r) {
    __shared__ int scnt[NREL];
    __shared__ int soff[NREL];
    __shared__ int scur[NREL];
    int t = threadIdx.x;
    if (t < NREL) { scnt[t] = 0; scur[t] = 0; }
    if (t == 0) g_done = 0;
    for (int i = t; i < MAXT; i += THREADS) g_tile_cnt[i] = 0;
    __syncthreads();

    int rv[M_TOT / THREADS];                    // cache r in registers (32 each)
    #pragma unroll
    for (int j = 0; j < M_TOT / THREADS; j++) {
        rv[j] = r[t + j * THREADS];
        atomicAdd(&scnt[rv[j]], 1);
    }
    __syncthreads();

    if (t == 0) {
        int off = 0, nt = 0;
        for (int rel = 0; rel < NREL; rel++) {
            soff[rel] = off;
            int c = scnt[rel];
            for (int s = 0; s < c; s += TM) {
                g_tile_rel[nt]   = rel;
                g_tile_start[nt] = off + s;
                g_tile_cnt[nt]   = min(TM, c - s);
                nt++;
            }
            off += c;
        }
    }
    __syncthreads();

    #pragma unroll
    for (int j = 0; j < M_TOT / THREADS; j++) {
        int rel = rv[j];
        int p = atomicAdd(&scur[rel], 1);
        g_sorted[soff[rel] + p] = t + j * THREADS;
    }
}

// ---------------- main fused kernel ----------------
struct SmemLayout {
    float  W[D * D];          // 64 KB, layout [e][j]
    float2 uv[D][TM + 1];     // [e][m] interleaved (u,v), padded row -> 33.8 KB
    float  rsh[D];            // relation embedding
    int    msh[TM];
    int    hidx[TM];
    int    pidx[TM];
    int    nidx[TM];
    float  regsh[TM];
    float  rsq;
};

__global__ void __launch_bounds__(THREADS, 2) k_main(
    const int*   __restrict__ h,
    const int*   __restrict__ pos_t,
    const int*   __restrict__ neg_t,
    const float* __restrict__ ent,
    const float* __restrict__ rel_emb,
    const float* __restrict__ rel_w,
    float*       __restrict__ out)
{
    extern __shared__ char smem_raw[];
    SmemLayout& S = *reinterpret_cast<SmemLayout*>(smem_raw);

    int tid = threadIdx.x;
    int cnt = g_tile_cnt[blockIdx.x];

    if (cnt > 0) {
        int rel   = g_tile_rel[blockIdx.x];
        int start = g_tile_start[blockIdx.x];

        // Stage indices + relation embedding + W (W is L2-hot: only 64 relations)
        if (tid < TM) {
            S.regsh[tid] = 0.f;
            if (tid < cnt) {
                int mo = g_sorted[start + tid];
                S.msh[tid]  = mo;
                S.hidx[tid] = h[mo];
                S.pidx[tid] = pos_t[mo];
                S.nidx[tid] = neg_t[mo];
            }
        }
        if (tid < D) S.rsh[tid] = rel_emb[rel * D + tid];

        const float4* Wg  = reinterpret_cast<const float4*>(rel_w + (size_t)rel * D * D);
        float4*       Ws4 = reinterpret_cast<float4*>(S.W);
        #pragma unroll
        for (int t = tid; t < (D * D) / 4; t += THREADS) Ws4[t] = Wg[t];
        __syncthreads();

        // rsq on warp 0
        if (tid < 32) {
            float s = 0.f;
            #pragma unroll
            for (int j = tid; j < D; j += 32) { float rv = S.rsh[j]; s += rv * rv; }
            #pragma unroll
            for (int o = 16; o; o >>= 1) s += __shfl_xor_sync(0xffffffffu, s, o);
            if (tid == 0) S.rsq = s;
        }

        // Gather embeddings: uv[e][i] = (h-p, h-n); reg squares accumulate
        for (int idx = tid; idx < TM * D; idx += THREADS) {
            int i = idx >> 7;
            int e = idx & (D - 1);
            float uo = 0.f, vo = 0.f, sq = 0.f;
            if (i < cnt) {
                float he = ent[(size_t)S.hidx[i] * D + e];
                float pe = ent[(size_t)S.pidx[i] * D + e];
                float ne = ent[(size_t)S.nidx[i] * D + e];
                uo = he - pe;
                vo = he - ne;
                sq = he * he + pe * pe + ne * ne;
            }
            S.uv[e][i] = make_float2(uo, vo);
            #pragma unroll
            for (int o = 16; o; o >>= 1) sq += __shfl_xor_sync(0xffffffffu, sq, o);
            if ((tid & 31) == 0 && i < cnt) atomicAdd(&S.regsh[i], sq);
        }
        __syncthreads();

        // Compute: warp mt handles m = mt + 8k (k<4); lane jt handles j = 4jt..4jt+3.
        // Packed FFMA2: each acc holds (uW_j, vW_j).
        int jt = tid & 31;
        int mt = tid >> 5;

        unsigned long long a[4][4];
        #pragma unroll
        for (int jj = 0; jj < 4; jj++)
            #pragma unroll
            for (int k = 0; k < 4; k++) a[jj][k] = 0ull;

        const float4* Wv = reinterpret_cast<const float4*>(S.W);
        const unsigned long long* uvp =
            reinterpret_cast<const unsigned long long*>(&S.uv[0][0]);

        #pragma unroll 4
        for (int e = 0; e < D; e++) {
            float4 w = Wv[e * 32 + jt];                   // coalesced LDS.128
            unsigned long long wxx = pack2(w.x, w.x);
            unsigned long long wyy = pack2(w.y, w.y);
            unsigned long long wzz = pack2(w.z, w.z);
            unsigned long long www = pack2(w.w, w.w);
            const unsigned long long* row = uvp + e * (TM + 1);
            #pragma unroll
            for (int k = 0; k < 4; k++) {
                unsigned long long uvk = row[mt + 8 * k]; // broadcast LDS.64
                a[0][k] = fma2(uvk, wxx, a[0][k]);
                a[1][k] = fma2(uvk, wyy, a[1][k]);
                a[2][k] = fma2(uvk, wzz, a[2][k]);
                a[3][k] = fma2(uvk, www, a[3][k]);
            }
        }

        float rj[4];
        #pragma unroll
        for (int jj = 0; jj < 4; jj++) rj[jj] = S.rsh[jt * 4 + jj];

        #pragma unroll
        for (int k = 0; k < 4; k++) {
            int i = mt + 8 * k;
            float pos = 0.f, neg = 0.f;
            #pragma unroll
            for (int jj = 0; jj < 4; jj++) {
                float au, av;
                unpack2(a[jj][k], au, av);
                float da = au + rj[jj];
                float db = av + rj[jj];
                pos += da * da;
                neg += db * db;
            }
            #pragma unroll
            for (int o = 16; o; o >>= 1) {
                pos += __shfl_xor_sync(0xffffffffu, pos, o);
                neg += __shfl_xor_sync(0xffffffffu, neg, o);
            }
            if (jt == 0 && i < cnt) {
                int mo = S.msh[i];
                float x = 0.5f * (pos - neg);                           // pos - neg score
                float loss = fmaxf(-x, 0.f) + log1pf(expf(-fabsf(x))); // softplus(-x)
                g_loss[mo] = loss;
                g_reg[mo]  = 0.5f * (S.regsh[i] + S.rsq);
            }
        }
    }

    // ---------- last-block final reduction (deterministic fixed-order sum) ----------
    __shared__ bool amLast;
    __threadfence();
    __syncthreads();
    if (tid == 0) {
        unsigned int prev = atomicAdd(&g_done, 1u);
        amLast = (prev == (unsigned int)(gridDim.x - 1));
    }
    __syncthreads();
    if (!amLast) return;
    __threadfence();

    __shared__ double sl[THREADS];
    __shared__ double sr[THREADS];
    double l = 0.0, rg = 0.0;
    for (int i = tid; i < M_TOT; i += THREADS) {
        l  += (double)g_loss[i];
        rg += (double)g_reg[i];
    }
    sl[tid] = l; sr[tid] = rg;
    __syncthreads();
    for (int s = THREADS / 2; s; s >>= 1) {
        if (tid < s) { sl[tid] += sl[tid + s]; sr[tid] += sr[tid + s]; }
        __syncthreads();
    }
    if (tid == 0) {
        double kg_loss = sl[0] / (double)M_TOT;
        double reg     = sr[0] / (double)M_TOT;
        out[0] = (float)(kg_loss + REG_LAMBDA * reg);
    }
}

// ---------------- launch ----------------
extern "C" void kernel_launch(void* const* d_in, const int* in_sizes, int n_in,
                              void* d_out, int out_size) {
    const int*   h       = (const int*)d_in[0];
    const int*   r       = (const int*)d_in[1];
    const int*   pos_t   = (const int*)d_in[2];
    const int*   neg_t   = (const int*)d_in[3];
    const float* ent     = (const float*)d_in[4];
    const float* rel_emb = (const float*)d_in[5];
    const float* rel_w   = (const float*)d_in[6];
    float* out = (float*)d_out;

    const int smem_bytes = (int)sizeof(SmemLayout);
    cudaFuncSetAttribute(k_main, cudaFuncAttributeMaxDynamicSharedMemorySize, smem_bytes);

    k_setup<<<1, THREADS>>>(r);
    k_main<<<MAXT, THREADS, smem_bytes>>>(h, pos_t, neg_t, ent, rel_emb, rel_w, out);
}

// round 3
// speedup vs baseline: 1.4310x; 1.3628x over previous
#include <cuda_runtime.h>
#include <math.h>

// Fixed problem shapes
#define M_TOT   8192
#define NREL    64
#define D       128
#define TM      16
#define MAXT    576          // sum ceil(cnt/16) <= 8192/16 + 64
#define STHREADS 256
#define THREADS 128
#define REG_LAMBDA 1e-5f

typedef unsigned long long u64;

// ---------------- device scratch ----------------
__device__ int   g_sorted[M_TOT];
__device__ int   g_tile_rel[MAXT];
__device__ int   g_tile_start[MAXT];
__device__ int   g_tile_cnt[MAXT];
__device__ float g_val[M_TOT];
__device__ unsigned int g_done;

// ---------------- packed f32x2 helpers ----------------
__device__ __forceinline__ u64 pack2(float x, float y) {
    u64 r;
    asm("mov.b64 %0, {%1, %2};" : "=l"(r) : "f"(x), "f"(y));
    return r;
}
__device__ __forceinline__ u64 fma2(u64 a, u64 b, u64 c) {
    u64 d;
    asm("fma.rn.f32x2 %0, %1, %2, %3;" : "=l"(d) : "l"(a), "l"(b), "l"(c));
    return d;
}
__device__ __forceinline__ void unpack2(u64 v, float& lo, float& hi) {
    asm("mov.b64 {%0, %1}, %2;" : "=f"(lo), "=f"(hi) : "l"(v));
}

// ---------------- fused setup: hist + scan + tile plan + counting-sort ----------------
__global__ void k_setup(const int* __restrict__ r) {
    __shared__ int scnt[NREL];
    __shared__ int soff[NREL];
    __shared__ int scur[NREL];
    __shared__ int stoff[NREL];
    int t = threadIdx.x;
    if (t < NREL) { scnt[t] = 0; scur[t] = 0; }
    if (t == 0) g_done = 0;
    for (int i = t; i < MAXT; i += STHREADS) g_tile_cnt[i] = 0;
    __syncthreads();

    int rv[M_TOT / STHREADS];
    #pragma unroll
    for (int j = 0; j < M_TOT / STHREADS; j++) {
        rv[j] = r[t + j * STHREADS];
        atomicAdd(&scnt[rv[j]], 1);
    }
    __syncthreads();

    if (t == 0) {                       // two tiny serial scans (64 iters)
        int off = 0, toff = 0;
        for (int rel = 0; rel < NREL; rel++) {
            soff[rel]  = off;
            stoff[rel] = toff;
            int c = scnt[rel];
            off  += c;
            toff += (c + TM - 1) / TM;
        }
    }
    __syncthreads();

    if (t < NREL) {                     // parallel tile-entry emission
        int c = scnt[t], o = soff[t], to = stoff[t];
        for (int s = 0; s < c; s += TM) {
            g_tile_rel[to]   = t;
            g_tile_start[to] = o + s;
            g_tile_cnt[to]   = min(TM, c - s);
            to++;
        }
    }
    __syncthreads();

    #pragma unroll
    for (int j = 0; j < M_TOT / STHREADS; j++) {
        int rel = rv[j];
        int p = atomicAdd(&scur[rel], 1);
        g_sorted[soff[rel] + p] = t + j * STHREADS;
    }
}

// ---------------- main fused kernel ----------------
struct SmemLayout {
    float2 uv[D][TM + 2];   // [e][m], row stride 18 keeps 16B alignment; 18.4 KB
    float  rsh[D];
    float  regsh[TM];
    int    msh[TM];
    int    hidx[TM];
    int    pidx[TM];
    int    nidx[TM];
    float  pp[4 * 8];       // per-(warp, k) partial pos
    float  pn[4 * 8];       // per-(warp, k) partial neg
    float  rsq;
};

__global__ void __launch_bounds__(THREADS, 6) k_main(
    const int*   __restrict__ h,
    const int*   __restrict__ pos_t,
    const int*   __restrict__ neg_t,
    const float* __restrict__ ent,
    const float* __restrict__ rel_emb,
    const float* __restrict__ rel_w,
    float*       __restrict__ out)
{
    __shared__ SmemLayout S;

    int tid = threadIdx.x;
    int w   = tid >> 5;
    int l   = tid & 31;
    int cnt = g_tile_cnt[blockIdx.x];

    if (cnt > 0) {
        int rel   = g_tile_rel[blockIdx.x];
        int start = g_tile_start[blockIdx.x];

        // ---- stage indices + relation embedding ----
        if (tid < TM && tid < cnt) {
            int mo = g_sorted[start + tid];
            S.msh[tid]  = mo;
            S.hidx[tid] = h[mo];
            S.pidx[tid] = pos_t[mo];
            S.nidx[tid] = neg_t[mo];
        }
        if (tid < D) S.rsh[tid] = rel_emb[rel * D + tid];
        __syncthreads();

        // ---- gather: warp w owns rows 4w..4w+3; lane-local sq accumulation ----
        float sqa[4];
        #pragma unroll
        for (int it = 0; it < 4; it++) {
            int i = w * 4 + it;
            float sq = 0.f;
            bool live = (i < cnt);
            long hb = live ? (long)S.hidx[i] * D : 0;
            long pb = live ? (long)S.pidx[i] * D : 0;
            long nb = live ? (long)S.nidx[i] * D : 0;
            #pragma unroll
            for (int q = 0; q < 4; q++) {
                int e = q * 32 + l;
                float uo = 0.f, vo = 0.f;
                if (live) {
                    float he = ent[hb + e];
                    float pe = ent[pb + e];
                    float ne = ent[nb + e];
                    uo = he - pe;
                    vo = he - ne;
                    sq += he * he + pe * pe + ne * ne;
                }
                S.uv[e][i] = make_float2(uo, vo);
            }
            sqa[it] = sq;
        }
        #pragma unroll
        for (int it = 0; it < 4; it++) {
            float s = sqa[it];
            #pragma unroll
            for (int o = 16; o; o >>= 1) s += __shfl_xor_sync(0xffffffffu, s, o);
            if (l == 0) S.regsh[w * 4 + it] = s;
        }
        // rsq on warp 0
        if (w == 0) {
            float s = 0.f;
            #pragma unroll
            for (int q = 0; q < 4; q++) { float x = S.rsh[q * 32 + l]; s += x * x; }
            #pragma unroll
            for (int o = 16; o; o >>= 1) s += __shfl_xor_sync(0xffffffffu, s, o);
            if (l == 0) S.rsq = s;
        }
        __syncthreads();

        // ---- compute: warp (grp, jhalf); lane covers j = jhalf*64 + 2l, 2l+1 ----
        // acc a0/a1[k] = packed (uW_j, vW_j) for m = mbase+k
        int jhalf = w & 1;
        int mbase = (w >> 1) * 8;

        u64 a0[8], a1[8];
        #pragma unroll
        for (int k = 0; k < 8; k++) { a0[k] = 0ull; a1[k] = 0ull; }

        // W streamed from L2: float2 per lane per e, stride 64 float2 per e-row
        const float2* wp = reinterpret_cast<const float2*>(rel_w)
                           + (size_t)rel * (D * D / 2) + jhalf * 32 + l;

        #pragma unroll 4
        for (int e = 0; e < D; e++) {
            float2 wv = wp[e * (D / 2)];
            u64 w0 = pack2(wv.x, wv.x);
            u64 w1 = pack2(wv.y, wv.y);
            const ulonglong2* row = reinterpret_cast<const ulonglong2*>(&S.uv[e][mbase]);
            #pragma unroll
            for (int p = 0; p < 4; p++) {
                ulonglong2 uv2 = row[p];              // broadcast LDS.128: (u,v) x 2 m's
                a0[2 * p]     = fma2(uv2.x, w0, a0[2 * p]);
                a1[2 * p]     = fma2(uv2.x, w1, a1[2 * p]);
                a0[2 * p + 1] = fma2(uv2.y, w0, a0[2 * p + 1]);
                a1[2 * p + 1] = fma2(uv2.y, w1, a1[2 * p + 1]);
            }
        }

        // ---- epilogue: per-m partial (pos, neg) over this warp's j-half ----
        float rj0 = S.rsh[jhalf * 64 + 2 * l];
        float rj1 = S.rsh[jhalf * 64 + 2 * l + 1];
        #pragma unroll
        for (int k = 0; k < 8; k++) {
            float x0, y0, x1, y1;
            unpack2(a0[k], x0, y0);
            unpack2(a1[k], x1, y1);
            float d0 = x0 + rj0, d1 = x1 + rj1;
            float e0 = y0 + rj0, e1 = y1 + rj1;
            float dp = d0 * d0 + d1 * d1;
            float dn = e0 * e0 + e1 * e1;
            #pragma unroll
            for (int o = 16; o; o >>= 1) {
                dp += __shfl_xor_sync(0xffffffffu, dp, o);
                dn += __shfl_xor_sync(0xffffffffu, dn, o);
            }
            if (l == k) { S.pp[w * 8 + k] = dp; S.pn[w * 8 + k] = dn; }
        }
        __syncthreads();

        // ---- combine j-halves, loss + reg, write per-m value ----
        if (tid < TM && tid < cnt) {
            int m = tid, grp = m >> 3, k = m & 7;
            float pos = S.pp[(2 * grp) * 8 + k] + S.pp[(2 * grp + 1) * 8 + k];
            float neg = S.pn[(2 * grp) * 8 + k] + S.pn[(2 * grp + 1) * 8 + k];
            float x = 0.5f * (pos - neg);
            float loss = fmaxf(-x, 0.f) + log1pf(expf(-fabsf(x)));   // softplus(-x)
            float val  = loss + REG_LAMBDA * 0.5f * (S.regsh[m] + S.rsq);
            g_val[S.msh[m]] = val;
        }
    }

    // ---------- last-block deterministic reduction ----------
    __shared__ bool amLast;
    __threadfence();
    __syncthreads();
    if (tid == 0) {
        unsigned int prev = atomicAdd(&g_done, 1u);
        amLast = (prev == (unsigned int)(gridDim.x - 1));
    }
    __syncthreads();
    if (!amLast) return;
    __threadfence();

    __shared__ double sd[THREADS];
    double acc = 0.0;
    for (int i = tid; i < M_TOT; i += THREADS) acc += (double)g_val[i];
    sd[tid] = acc;
    __syncthreads();
    for (int s = THREADS / 2; s; s >>= 1) {
        if (tid < s) sd[tid] += sd[tid + s];
        __syncthreads();
    }
    if (tid == 0) out[0] = (float)(sd[0] / (double)M_TOT);
}

// ---------------- launch ----------------
extern "C" void kernel_launch(void* const* d_in, const int* in_sizes, int n_in,
                              void* d_out, int out_size) {
    const int*   h       = (const int*)d_in[0];
    const int*   r       = (const int*)d_in[1];
    const int*   pos_t   = (const int*)d_in[2];
    const int*   neg_t   = (const int*)d_in[3];
    const float* ent     = (const float*)d_in[4];
    const float* rel_emb = (const float*)d_in[5];
    const float* rel_w   = (const float*)d_in[6];
    float* out = (float*)d_out;

    k_setup<<<1, STHREADS>>>(r);
    k_main<<<MAXT, THREADS>>>(h, pos_t, neg_t, ent, rel_emb, rel_w, out);
}